// round 4
// baseline (speedup 1.0000x reference)
#include <cuda_runtime.h>
#include <cstddef>

#define TPB 128
#define SMSTRIDE 82           // >= max stage chunk (80), keeps 2-way-max bank conflicts

static constexpr int NB = 131072;

// ---------------------------------------------------------------------------
// Compile-time Clebsch-Gordan coefficients (Racah formula), double precision,
// evaluated entirely by the compiler. Includes a constexpr Newton sqrt since
// std::sqrt is not constexpr in C++17.
// ---------------------------------------------------------------------------
__host__ __device__ constexpr double factd(int n) {
    double r = 1.0;
    for (int i = 2; i <= n; ++i) r *= (double)i;
    return r;
}
__host__ __device__ constexpr double csqrt(double x) {
    if (x <= 0.0) return 0.0;
    double g = x > 1.0 ? x : 1.0;
    for (int i = 0; i < 100; ++i) g = 0.5 * (g + x / g);
    return g;
}
__host__ __device__ constexpr int iabs_c(int x) { return x < 0 ? -x : x; }
__host__ __device__ constexpr int imin6(int a, int b, int c, int d, int e, int f) {
    int m = a;
    if (b < m) m = b; if (c < m) m = c; if (d < m) m = d;
    if (e < m) m = e; if (f < m) m = f;
    return m;
}

__host__ __device__ constexpr double cgco(int j1, int m1, int j2, int m2, int j, int m) {
    if (m1 + m2 != m) return 0.0;
    if (j < iabs_c(j1 - j2) || j > j1 + j2) return 0.0;
    if (iabs_c(m) > j || iabs_c(m1) > j1 || iabs_c(m2) > j2) return 0.0;
    double pre = csqrt((2.0 * j + 1.0) * factd(j1 + j2 - j) * factd(j + j1 - j2) *
                       factd(j + j2 - j1) / factd(j1 + j2 + j + 1));
    pre *= csqrt(factd(j + m) * factd(j - m) * factd(j1 + m1) * factd(j1 - m1) *
                 factd(j2 + m2) * factd(j2 - m2));
    double s = 0.0;
    for (int k = 0; k <= j1 + j2 - j; ++k) {
        const int d1 = k;
        const int d2 = j1 + j2 - j - k;
        const int d3 = j1 - m1 - k;
        const int d4 = j2 + m2 - k;
        const int d5 = j - j2 + m1 + k;
        const int d6 = j - j1 - m2 + k;
        if (imin6(d1, d2, d3, d4, d5, d6) < 0) continue;
        const double denom = factd(d1) * factd(d2) * factd(d3) * factd(d4) * factd(d5) * factd(d6);
        s += ((k & 1) ? -1.0 : 1.0) / denom;
    }
    return pre * s;
}

// Register-array offset for input part l (sizes 1,3,5,7 -> offsets 0,1,4,9)
template <int L>
__host__ __device__ constexpr int xoff() { return L == 0 ? 0 : (L == 1 ? 1 : (L == 2 ? 4 : 9)); }

// ---------------------------------------------------------------------------
// Template-unrolled accumulation: sum over m1 for one (l1,l2,l,m) entry set.
// All CG coefficients become FFMA immediates; zero coefficients are pruned.
// ---------------------------------------------------------------------------
template <int L1, int L2, int L, int M, int M1>
__device__ __forceinline__ void acc_m1(float& fr, float& fi, const float* xr, const float* xi) {
    constexpr int M2 = M - M1;
    if constexpr (M2 >= -L2 && M2 <= L2) {
        constexpr double Cd = cgco(L1, M1, L2, M2, L, M);
        if constexpr (Cd != 0.0) {
            constexpr float C = (float)Cd;
            const float a = xr[xoff<L1>() + M1 + L1];
            const float b = xi[xoff<L1>() + M1 + L1];
            const float c = xr[xoff<L2>() + M2 + L2];
            const float d = xi[xoff<L2>() + M2 + L2];
            const float pr = fmaf(-b, d, a * c);   // Re(x*y)
            const float pi = fmaf( b, c, a * d);   // Im(x*y)
            fr = fmaf(C, pr, fr);
            fi = fmaf(C, pi, fi);
        }
    }
    if constexpr (M1 < L1) acc_m1<L1, L2, L, M, M1 + 1>(fr, fi, xr, xi);
}

// One fragment (l1,l2) contributing to output l, for m in [MLO, MHI].
// Writes (fr,fi) into the thread's smem row at chunk position ((m-MLO)*TAU+FI)*2.
template <int L, int TAU, int FI, int L1, int L2, int MLO, int MHI, int M>
__device__ __forceinline__ void frag_ms(float* row, const float* xr, const float* xi) {
    float fr = 0.0f, fi2 = 0.0f;
    acc_m1<L1, L2, L, M, (-L1)>(fr, fi2, xr, xi);
    row[((M - MLO) * TAU + FI) * 2 + 0] = fr;
    row[((M - MLO) * TAU + FI) * 2 + 1] = fi2;
    if constexpr (M < MHI) frag_ms<L, TAU, FI, L1, L2, MLO, MHI, M + 1>(row, xr, xi);
}

// Cooperative coalesced store of one staged chunk: smem tile -> out rows.
// CHUNK floats per element (even), OFF = float offset inside the 512-float row.
template <int CHUNK, int OFF>
__device__ __forceinline__ void store_stage(const float* sm, float* __restrict__ out,
                                            int base, int tid) {
    __syncthreads();
    constexpr int C2 = CHUNK / 2;
    #pragma unroll 4
    for (int u = tid; u < TPB * C2; u += TPB) {
        const int e = u / C2;
        const int j = u - e * C2;
        const float2 v = *reinterpret_cast<const float2*>(sm + e * SMSTRIDE + 2 * j);
        *reinterpret_cast<float2*>(out + (size_t)(base + e) * 512 + OFF + 2 * j) = v;
    }
    __syncthreads();
}

// ---------------------------------------------------------------------------
// Main kernel: one thread per batch element.
// Output layout per element (512 floats):
//   l=0: off   0, tau 4   | l=1: off   8, tau 9 | l=2: off  62, tau 11
//   l=3: off 172, tau 10  | l=4: off 312, tau 6 | l=5: off 420, tau 3
//   l=6: off 486, tau 1
// Large chunks are split by m so the smem stage stays <= 80 floats/element.
// ---------------------------------------------------------------------------
__global__ void __launch_bounds__(TPB, 4)
cgprod_kernel(const float* __restrict__ x0, const float* __restrict__ x1,
              const float* __restrict__ x2, const float* __restrict__ x3,
              float* __restrict__ out) {
    __shared__ float sm[TPB * SMSTRIDE];
    const int tid  = threadIdx.x;
    const int base = blockIdx.x * TPB;
    const int b    = base + tid;

    float xr[16], xi[16];
    {
        const float2 v = reinterpret_cast<const float2*>(x0)[b];
        xr[0] = v.x; xi[0] = v.y;
    }
    {
        const float2* p = reinterpret_cast<const float2*>(x1) + (size_t)b * 3;
        #pragma unroll
        for (int k = 0; k < 3; ++k) { const float2 v = p[k]; xr[1 + k] = v.x; xi[1 + k] = v.y; }
    }
    {
        const float2* p = reinterpret_cast<const float2*>(x2) + (size_t)b * 5;
        #pragma unroll
        for (int k = 0; k < 5; ++k) { const float2 v = p[k]; xr[4 + k] = v.x; xi[4 + k] = v.y; }
    }
    {
        const float2* p = reinterpret_cast<const float2*>(x3) + (size_t)b * 7;
        #pragma unroll
        for (int k = 0; k < 7; ++k) { const float2 v = p[k]; xr[9 + k] = v.x; xi[9 + k] = v.y; }
    }

    float* row = sm + tid * SMSTRIDE;

    // ---- l = 0 (tau=4), m = 0, chunk 8 @ off 0 ----
    {
        constexpr int L = 0, TAU = 4, MLO = 0, MHI = 0;
        frag_ms<L, TAU, 0, 0, 0, MLO, MHI, MLO>(row, xr, xi);
        frag_ms<L, TAU, 1, 1, 1, MLO, MHI, MLO>(row, xr, xi);
        frag_ms<L, TAU, 2, 2, 2, MLO, MHI, MLO>(row, xr, xi);
        frag_ms<L, TAU, 3, 3, 3, MLO, MHI, MLO>(row, xr, xi);
    }
    store_stage<8, 0>(sm, out, base, tid);

    // ---- l = 1 (tau=9), m = -1..1, chunk 54 @ off 8 ----
    {
        constexpr int L = 1, TAU = 9, MLO = -1, MHI = 1;
        frag_ms<L, TAU, 0, 0, 1, MLO, MHI, MLO>(row, xr, xi);
        frag_ms<L, TAU, 1, 1, 0, MLO, MHI, MLO>(row, xr, xi);
        frag_ms<L, TAU, 2, 1, 1, MLO, MHI, MLO>(row, xr, xi);
        frag_ms<L, TAU, 3, 1, 2, MLO, MHI, MLO>(row, xr, xi);
        frag_ms<L, TAU, 4, 2, 1, MLO, MHI, MLO>(row, xr, xi);
        frag_ms<L, TAU, 5, 2, 2, MLO, MHI, MLO>(row, xr, xi);
        frag_ms<L, TAU, 6, 2, 3, MLO, MHI, MLO>(row, xr, xi);
        frag_ms<L, TAU, 7, 3, 2, MLO, MHI, MLO>(row, xr, xi);
        frag_ms<L, TAU, 8, 3, 3, MLO, MHI, MLO>(row, xr, xi);
    }
    store_stage<54, 8>(sm, out, base, tid);

    // ---- l = 2 (tau=11), stage A: m = -2..0, chunk 66 @ off 62 ----
    {
        constexpr int L = 2, TAU = 11, MLO = -2, MHI = 0;
        frag_ms<L, TAU,  0, 0, 2, MLO, MHI, MLO>(row, xr, xi);
        frag_ms<L, TAU,  1, 1, 1, MLO, MHI, MLO>(row, xr, xi);
        frag_ms<L, TAU,  2, 1, 2, MLO, MHI, MLO>(row, xr, xi);
        frag_ms<L, TAU,  3, 1, 3, MLO, MHI, MLO>(row, xr, xi);
        frag_ms<L, TAU,  4, 2, 0, MLO, MHI, MLO>(row, xr, xi);
        frag_ms<L, TAU,  5, 2, 1, MLO, MHI, MLO>(row, xr, xi);
        frag_ms<L, TAU,  6, 2, 2, MLO, MHI, MLO>(row, xr, xi);
        frag_ms<L, TAU,  7, 2, 3, MLO, MHI, MLO>(row, xr, xi);
        frag_ms<L, TAU,  8, 3, 1, MLO, MHI, MLO>(row, xr, xi);
        frag_ms<L, TAU,  9, 3, 2, MLO, MHI, MLO>(row, xr, xi);
        frag_ms<L, TAU, 10, 3, 3, MLO, MHI, MLO>(row, xr, xi);
    }
    store_stage<66, 62>(sm, out, base, tid);

    // ---- l = 2, stage B: m = 1..2, chunk 44 @ off 128 ----
    {
        constexpr int L = 2, TAU = 11, MLO = 1, MHI = 2;
        frag_ms<L, TAU,  0, 0, 2, MLO, MHI, MLO>(row, xr, xi);
        frag_ms<L, TAU,  1, 1, 1, MLO, MHI, MLO>(row, xr, xi);
        frag_ms<L, TAU,  2, 1, 2, MLO, MHI, MLO>(row, xr, xi);
        frag_ms<L, TAU,  3, 1, 3, MLO, MHI, MLO>(row, xr, xi);
        frag_ms<L, TAU,  4, 2, 0, MLO, MHI, MLO>(row, xr, xi);
        frag_ms<L, TAU,  5, 2, 1, MLO, MHI, MLO>(row, xr, xi);
        frag_ms<L, TAU,  6, 2, 2, MLO, MHI, MLO>(row, xr, xi);
        frag_ms<L, TAU,  7, 2, 3, MLO, MHI, MLO>(row, xr, xi);
        frag_ms<L, TAU,  8, 3, 1, MLO, MHI, MLO>(row, xr, xi);
        frag_ms<L, TAU,  9, 3, 2, MLO, MHI, MLO>(row, xr, xi);
        frag_ms<L, TAU, 10, 3, 3, MLO, MHI, MLO>(row, xr, xi);
    }
    store_stage<44, 128>(sm, out, base, tid);

    // ---- l = 3 (tau=10), stage A: m = -3..0, chunk 80 @ off 172 ----
    {
        constexpr int L = 3, TAU = 10, MLO = -3, MHI = 0;
        frag_ms<L, TAU, 0, 0, 3, MLO, MHI, MLO>(row, xr, xi);
        frag_ms<L, TAU, 1, 1, 2, MLO, MHI, MLO>(row, xr, xi);
        frag_ms<L, TAU, 2, 1, 3, MLO, MHI, MLO>(row, xr, xi);
        frag_ms<L, TAU, 3, 2, 1, MLO, MHI, MLO>(row, xr, xi);
        frag_ms<L, TAU, 4, 2, 2, MLO, MHI, MLO>(row, xr, xi);
        frag_ms<L, TAU, 5, 2, 3, MLO, MHI, MLO>(row, xr, xi);
        frag_ms<L, TAU, 6, 3, 0, MLO, MHI, MLO>(row, xr, xi);
        frag_ms<L, TAU, 7, 3, 1, MLO, MHI, MLO>(row, xr, xi);
        frag_ms<L, TAU, 8, 3, 2, MLO, MHI, MLO>(row, xr, xi);
        frag_ms<L, TAU, 9, 3, 3, MLO, MHI, MLO>(row, xr, xi);
    }
    store_stage<80, 172>(sm, out, base, tid);

    // ---- l = 3, stage B: m = 1..3, chunk 60 @ off 252 ----
    {
        constexpr int L = 3, TAU = 10, MLO = 1, MHI = 3;
        frag_ms<L, TAU, 0, 0, 3, MLO, MHI, MLO>(row, xr, xi);
        frag_ms<L, TAU, 1, 1, 2, MLO, MHI, MLO>(row, xr, xi);
        frag_ms<L, TAU, 2, 1, 3, MLO, MHI, MLO>(row, xr, xi);
        frag_ms<L, TAU, 3, 2, 1, MLO, MHI, MLO>(row, xr, xi);
        frag_ms<L, TAU, 4, 2, 2, MLO, MHI, MLO>(row, xr, xi);
        frag_ms<L, TAU, 5, 2, 3, MLO, MHI, MLO>(row, xr, xi);
        frag_ms<L, TAU, 6, 3, 0, MLO, MHI, MLO>(row, xr, xi);
        frag_ms<L, TAU, 7, 3, 1, MLO, MHI, MLO>(row, xr, xi);
        frag_ms<L, TAU, 8, 3, 2, MLO, MHI, MLO>(row, xr, xi);
        frag_ms<L, TAU, 9, 3, 3, MLO, MHI, MLO>(row, xr, xi);
    }
    store_stage<60, 252>(sm, out, base, tid);

    // ---- l = 4 (tau=6), stage A: m = -4..0, chunk 60 @ off 312 ----
    {
        constexpr int L = 4, TAU = 6, MLO = -4, MHI = 0;
        frag_ms<L, TAU, 0, 1, 3, MLO, MHI, MLO>(row, xr, xi);
        frag_ms<L, TAU, 1, 2, 2, MLO, MHI, MLO>(row, xr, xi);
        frag_ms<L, TAU, 2, 2, 3, MLO, MHI, MLO>(row, xr, xi);
        frag_ms<L, TAU, 3, 3, 1, MLO, MHI, MLO>(row, xr, xi);
        frag_ms<L, TAU, 4, 3, 2, MLO, MHI, MLO>(row, xr, xi);
        frag_ms<L, TAU, 5, 3, 3, MLO, MHI, MLO>(row, xr, xi);
    }
    store_stage<60, 312>(sm, out, base, tid);

    // ---- l = 4, stage B: m = 1..4, chunk 48 @ off 372 ----
    {
        constexpr int L = 4, TAU = 6, MLO = 1, MHI = 4;
        frag_ms<L, TAU, 0, 1, 3, MLO, MHI, MLO>(row, xr, xi);
        frag_ms<L, TAU, 1, 2, 2, MLO, MHI, MLO>(row, xr, xi);
        frag_ms<L, TAU, 2, 2, 3, MLO, MHI, MLO>(row, xr, xi);
        frag_ms<L, TAU, 3, 3, 1, MLO, MHI, MLO>(row, xr, xi);
        frag_ms<L, TAU, 4, 3, 2, MLO, MHI, MLO>(row, xr, xi);
        frag_ms<L, TAU, 5, 3, 3, MLO, MHI, MLO>(row, xr, xi);
    }
    store_stage<48, 372>(sm, out, base, tid);

    // ---- l = 5 (tau=3), m = -5..5, chunk 66 @ off 420 ----
    {
        constexpr int L = 5, TAU = 3, MLO = -5, MHI = 5;
        frag_ms<L, TAU, 0, 2, 3, MLO, MHI, MLO>(row, xr, xi);
        frag_ms<L, TAU, 1, 3, 2, MLO, MHI, MLO>(row, xr, xi);
        frag_ms<L, TAU, 2, 3, 3, MLO, MHI, MLO>(row, xr, xi);
    }
    store_stage<66, 420>(sm, out, base, tid);

    // ---- l = 6 (tau=1), m = -6..6, chunk 26 @ off 486 ----
    {
        constexpr int L = 6, TAU = 1, MLO = -6, MHI = 6;
        frag_ms<L, TAU, 0, 3, 3, MLO, MHI, MLO>(row, xr, xi);
    }
    store_stage<26, 486>(sm, out, base, tid);
}

extern "C" void kernel_launch(void* const* d_in, const int* in_sizes, int n_in,
                              void* d_out, int out_size) {
    // Defensive: map inputs by element count (all four are distinct).
    const float* xp[4] = {nullptr, nullptr, nullptr, nullptr};
    for (int i = 0; i < n_in && i < 8; ++i) {
        const int s = in_sizes[i];
        if      (s == NB * 2)  xp[0] = (const float*)d_in[i];
        else if (s == NB * 6)  xp[1] = (const float*)d_in[i];
        else if (s == NB * 10) xp[2] = (const float*)d_in[i];
        else if (s == NB * 14) xp[3] = (const float*)d_in[i];
    }
    cgprod_kernel<<<NB / TPB, TPB>>>(xp[0], xp[1], xp[2], xp[3], (float*)d_out);
}

// round 5
// speedup vs baseline: 1.2459x; 1.2459x over previous
#include <cuda_runtime.h>
#include <cstddef>

#define TPB 128
#define SMSTRIDE 82           // >= max stage chunk (80), keeps 2-way-max bank conflicts

static constexpr int NB = 131072;

// ---------------------------------------------------------------------------
// Compile-time Clebsch-Gordan coefficients (Racah formula), double precision,
// evaluated entirely by the compiler. Includes a constexpr Newton sqrt since
// std::sqrt is not constexpr in C++17.
// ---------------------------------------------------------------------------
__host__ __device__ constexpr double factd(int n) {
    double r = 1.0;
    for (int i = 2; i <= n; ++i) r *= (double)i;
    return r;
}
__host__ __device__ constexpr double csqrt(double x) {
    if (x <= 0.0) return 0.0;
    double g = x > 1.0 ? x : 1.0;
    for (int i = 0; i < 100; ++i) g = 0.5 * (g + x / g);
    return g;
}
__host__ __device__ constexpr int iabs_c(int x) { return x < 0 ? -x : x; }
__host__ __device__ constexpr int imin6(int a, int b, int c, int d, int e, int f) {
    int m = a;
    if (b < m) m = b; if (c < m) m = c; if (d < m) m = d;
    if (e < m) m = e; if (f < m) m = f;
    return m;
}

__host__ __device__ constexpr double cgco(int j1, int m1, int j2, int m2, int j, int m) {
    if (m1 + m2 != m) return 0.0;
    if (j < iabs_c(j1 - j2) || j > j1 + j2) return 0.0;
    if (iabs_c(m) > j || iabs_c(m1) > j1 || iabs_c(m2) > j2) return 0.0;
    double pre = csqrt((2.0 * j + 1.0) * factd(j1 + j2 - j) * factd(j + j1 - j2) *
                       factd(j + j2 - j1) / factd(j1 + j2 + j + 1));
    pre *= csqrt(factd(j + m) * factd(j - m) * factd(j1 + m1) * factd(j1 - m1) *
                 factd(j2 + m2) * factd(j2 - m2));
    double s = 0.0;
    for (int k = 0; k <= j1 + j2 - j; ++k) {
        const int d1 = k;
        const int d2 = j1 + j2 - j - k;
        const int d3 = j1 - m1 - k;
        const int d4 = j2 + m2 - k;
        const int d5 = j - j2 + m1 + k;
        const int d6 = j - j1 - m2 + k;
        if (imin6(d1, d2, d3, d4, d5, d6) < 0) continue;
        const double denom = factd(d1) * factd(d2) * factd(d3) * factd(d4) * factd(d5) * factd(d6);
        s += ((k & 1) ? -1.0 : 1.0) / denom;
    }
    return pre * s;
}

// Register-array offset for input part l (sizes 1,3,5,7 -> offsets 0,1,4,9)
template <int L>
__host__ __device__ constexpr int xoff() { return L == 0 ? 0 : (L == 1 ? 1 : (L == 2 ? 4 : 9)); }

// ---------------------------------------------------------------------------
// Template-unrolled accumulation: sum over m1 for one (l1,l2,l,m) entry set.
// All CG coefficients become FFMA immediates; zero coefficients are pruned.
// ---------------------------------------------------------------------------
template <int L1, int L2, int L, int M, int M1>
__device__ __forceinline__ void acc_m1(float& fr, float& fi, const float* xr, const float* xi) {
    constexpr int M2 = M - M1;
    if constexpr (M2 >= -L2 && M2 <= L2) {
        constexpr double Cd = cgco(L1, M1, L2, M2, L, M);
        if constexpr (Cd != 0.0) {
            constexpr float C = (float)Cd;
            const float a = xr[xoff<L1>() + M1 + L1];
            const float b = xi[xoff<L1>() + M1 + L1];
            const float c = xr[xoff<L2>() + M2 + L2];
            const float d = xi[xoff<L2>() + M2 + L2];
            const float pr = fmaf(-b, d, a * c);   // Re(x*y)
            const float pi = fmaf( b, c, a * d);   // Im(x*y)
            fr = fmaf(C, pr, fr);
            fi = fmaf(C, pi, fi);
        }
    }
    if constexpr (M1 < L1) acc_m1<L1, L2, L, M, M1 + 1>(fr, fi, xr, xi);
}

// One fragment (l1,l2) contributing to output l, for m in [MLO, MHI].
// Writes (fr,fi) into the thread's smem row at chunk position ((m-MLO)*TAU+FI)*2.
template <int L, int TAU, int FI, int L1, int L2, int MLO, int MHI, int M>
__device__ __forceinline__ void frag_ms(float* row, const float* xr, const float* xi) {
    float fr = 0.0f, fi2 = 0.0f;
    acc_m1<L1, L2, L, M, (-L1)>(fr, fi2, xr, xi);
    row[((M - MLO) * TAU + FI) * 2 + 0] = fr;
    row[((M - MLO) * TAU + FI) * 2 + 1] = fi2;
    if constexpr (M < MHI) frag_ms<L, TAU, FI, L1, L2, MLO, MHI, M + 1>(row, xr, xi);
}

// Cooperative coalesced store of one staged chunk: smem tile -> out rows.
// CHUNK floats per element (even), OFF = float offset inside the 512-float row.
template <int CHUNK, int OFF>
__device__ __forceinline__ void store_stage(const float* sm, float* __restrict__ out,
                                            int base, int tid) {
    __syncthreads();
    constexpr int C2 = CHUNK / 2;
    #pragma unroll 4
    for (int u = tid; u < TPB * C2; u += TPB) {
        const int e = u / C2;
        const int j = u - e * C2;
        const float2 v = *reinterpret_cast<const float2*>(sm + e * SMSTRIDE + 2 * j);
        *reinterpret_cast<float2*>(out + (size_t)(base + e) * 512 + OFF + 2 * j) = v;
    }
    __syncthreads();
}

// ---------------------------------------------------------------------------
// Main kernel: one thread per batch element.
// Output layout per element (512 floats):
//   l=0: off   0, tau 4   | l=1: off   8, tau 9 | l=2: off  62, tau 11
//   l=3: off 172, tau 10  | l=4: off 312, tau 6 | l=5: off 420, tau 3
//   l=6: off 486, tau 1
// Large chunks are split by m so the smem stage stays <= 80 floats/element.
// ---------------------------------------------------------------------------
__global__ void __launch_bounds__(TPB, 4)
cgprod_kernel(const float* __restrict__ x0, const float* __restrict__ x1,
              const float* __restrict__ x2, const float* __restrict__ x3,
              float* __restrict__ out) {
    __shared__ float sm[TPB * SMSTRIDE];
    const int tid  = threadIdx.x;
    const int base = blockIdx.x * TPB;
    const int b    = base + tid;

    float xr[16], xi[16];
    {
        const float2 v = reinterpret_cast<const float2*>(x0)[b];
        xr[0] = v.x; xi[0] = v.y;
    }
    {
        const float2* p = reinterpret_cast<const float2*>(x1) + (size_t)b * 3;
        #pragma unroll
        for (int k = 0; k < 3; ++k) { const float2 v = p[k]; xr[1 + k] = v.x; xi[1 + k] = v.y; }
    }
    {
        const float2* p = reinterpret_cast<const float2*>(x2) + (size_t)b * 5;
        #pragma unroll
        for (int k = 0; k < 5; ++k) { const float2 v = p[k]; xr[4 + k] = v.x; xi[4 + k] = v.y; }
    }
    {
        const float2* p = reinterpret_cast<const float2*>(x3) + (size_t)b * 7;
        #pragma unroll
        for (int k = 0; k < 7; ++k) { const float2 v = p[k]; xr[9 + k] = v.x; xi[9 + k] = v.y; }
    }

    float* row = sm + tid * SMSTRIDE;

    // ---- l = 0 (tau=4), m = 0, chunk 8 @ off 0 ----
    {
        constexpr int L = 0, TAU = 4, MLO = 0, MHI = 0;
        frag_ms<L, TAU, 0, 0, 0, MLO, MHI, MLO>(row, xr, xi);
        frag_ms<L, TAU, 1, 1, 1, MLO, MHI, MLO>(row, xr, xi);
        frag_ms<L, TAU, 2, 2, 2, MLO, MHI, MLO>(row, xr, xi);
        frag_ms<L, TAU, 3, 3, 3, MLO, MHI, MLO>(row, xr, xi);
    }
    store_stage<8, 0>(sm, out, base, tid);

    // ---- l = 1 (tau=9), m = -1..1, chunk 54 @ off 8 ----
    {
        constexpr int L = 1, TAU = 9, MLO = -1, MHI = 1;
        frag_ms<L, TAU, 0, 0, 1, MLO, MHI, MLO>(row, xr, xi);
        frag_ms<L, TAU, 1, 1, 0, MLO, MHI, MLO>(row, xr, xi);
        frag_ms<L, TAU, 2, 1, 1, MLO, MHI, MLO>(row, xr, xi);
        frag_ms<L, TAU, 3, 1, 2, MLO, MHI, MLO>(row, xr, xi);
        frag_ms<L, TAU, 4, 2, 1, MLO, MHI, MLO>(row, xr, xi);
        frag_ms<L, TAU, 5, 2, 2, MLO, MHI, MLO>(row, xr, xi);
        frag_ms<L, TAU, 6, 2, 3, MLO, MHI, MLO>(row, xr, xi);
        frag_ms<L, TAU, 7, 3, 2, MLO, MHI, MLO>(row, xr, xi);
        frag_ms<L, TAU, 8, 3, 3, MLO, MHI, MLO>(row, xr, xi);
    }
    store_stage<54, 8>(sm, out, base, tid);

    // ---- l = 2 (tau=11), stage A: m = -2..0, chunk 66 @ off 62 ----
    {
        constexpr int L = 2, TAU = 11, MLO = -2, MHI = 0;
        frag_ms<L, TAU,  0, 0, 2, MLO, MHI, MLO>(row, xr, xi);
        frag_ms<L, TAU,  1, 1, 1, MLO, MHI, MLO>(row, xr, xi);
        frag_ms<L, TAU,  2, 1, 2, MLO, MHI, MLO>(row, xr, xi);
        frag_ms<L, TAU,  3, 1, 3, MLO, MHI, MLO>(row, xr, xi);
        frag_ms<L, TAU,  4, 2, 0, MLO, MHI, MLO>(row, xr, xi);
        frag_ms<L, TAU,  5, 2, 1, MLO, MHI, MLO>(row, xr, xi);
        frag_ms<L, TAU,  6, 2, 2, MLO, MHI, MLO>(row, xr, xi);
        frag_ms<L, TAU,  7, 2, 3, MLO, MHI, MLO>(row, xr, xi);
        frag_ms<L, TAU,  8, 3, 1, MLO, MHI, MLO>(row, xr, xi);
        frag_ms<L, TAU,  9, 3, 2, MLO, MHI, MLO>(row, xr, xi);
        frag_ms<L, TAU, 10, 3, 3, MLO, MHI, MLO>(row, xr, xi);
    }
    store_stage<66, 62>(sm, out, base, tid);

    // ---- l = 2, stage B: m = 1..2, chunk 44 @ off 128 ----
    {
        constexpr int L = 2, TAU = 11, MLO = 1, MHI = 2;
        frag_ms<L, TAU,  0, 0, 2, MLO, MHI, MLO>(row, xr, xi);
        frag_ms<L, TAU,  1, 1, 1, MLO, MHI, MLO>(row, xr, xi);
        frag_ms<L, TAU,  2, 1, 2, MLO, MHI, MLO>(row, xr, xi);
        frag_ms<L, TAU,  3, 1, 3, MLO, MHI, MLO>(row, xr, xi);
        frag_ms<L, TAU,  4, 2, 0, MLO, MHI, MLO>(row, xr, xi);
        frag_ms<L, TAU,  5, 2, 1, MLO, MHI, MLO>(row, xr, xi);
        frag_ms<L, TAU,  6, 2, 2, MLO, MHI, MLO>(row, xr, xi);
        frag_ms<L, TAU,  7, 2, 3, MLO, MHI, MLO>(row, xr, xi);
        frag_ms<L, TAU,  8, 3, 1, MLO, MHI, MLO>(row, xr, xi);
        frag_ms<L, TAU,  9, 3, 2, MLO, MHI, MLO>(row, xr, xi);
        frag_ms<L, TAU, 10, 3, 3, MLO, MHI, MLO>(row, xr, xi);
    }
    store_stage<44, 128>(sm, out, base, tid);

    // ---- l = 3 (tau=10), stage A: m = -3..0, chunk 80 @ off 172 ----
    {
        constexpr int L = 3, TAU = 10, MLO = -3, MHI = 0;
        frag_ms<L, TAU, 0, 0, 3, MLO, MHI, MLO>(row, xr, xi);
        frag_ms<L, TAU, 1, 1, 2, MLO, MHI, MLO>(row, xr, xi);
        frag_ms<L, TAU, 2, 1, 3, MLO, MHI, MLO>(row, xr, xi);
        frag_ms<L, TAU, 3, 2, 1, MLO, MHI, MLO>(row, xr, xi);
        frag_ms<L, TAU, 4, 2, 2, MLO, MHI, MLO>(row, xr, xi);
        frag_ms<L, TAU, 5, 2, 3, MLO, MHI, MLO>(row, xr, xi);
        frag_ms<L, TAU, 6, 3, 0, MLO, MHI, MLO>(row, xr, xi);
        frag_ms<L, TAU, 7, 3, 1, MLO, MHI, MLO>(row, xr, xi);
        frag_ms<L, TAU, 8, 3, 2, MLO, MHI, MLO>(row, xr, xi);
        frag_ms<L, TAU, 9, 3, 3, MLO, MHI, MLO>(row, xr, xi);
    }
    store_stage<80, 172>(sm, out, base, tid);

    // ---- l = 3, stage B: m = 1..3, chunk 60 @ off 252 ----
    {
        constexpr int L = 3, TAU = 10, MLO = 1, MHI = 3;
        frag_ms<L, TAU, 0, 0, 3, MLO, MHI, MLO>(row, xr, xi);
        frag_ms<L, TAU, 1, 1, 2, MLO, MHI, MLO>(row, xr, xi);
        frag_ms<L, TAU, 2, 1, 3, MLO, MHI, MLO>(row, xr, xi);
        frag_ms<L, TAU, 3, 2, 1, MLO, MHI, MLO>(row, xr, xi);
        frag_ms<L, TAU, 4, 2, 2, MLO, MHI, MLO>(row, xr, xi);
        frag_ms<L, TAU, 5, 2, 3, MLO, MHI, MLO>(row, xr, xi);
        frag_ms<L, TAU, 6, 3, 0, MLO, MHI, MLO>(row, xr, xi);
        frag_ms<L, TAU, 7, 3, 1, MLO, MHI, MLO>(row, xr, xi);
        frag_ms<L, TAU, 8, 3, 2, MLO, MHI, MLO>(row, xr, xi);
        frag_ms<L, TAU, 9, 3, 3, MLO, MHI, MLO>(row, xr, xi);
    }
    store_stage<60, 252>(sm, out, base, tid);

    // ---- l = 4 (tau=6), stage A: m = -4..0, chunk 60 @ off 312 ----
    {
        constexpr int L = 4, TAU = 6, MLO = -4, MHI = 0;
        frag_ms<L, TAU, 0, 1, 3, MLO, MHI, MLO>(row, xr, xi);
        frag_ms<L, TAU, 1, 2, 2, MLO, MHI, MLO>(row, xr, xi);
        frag_ms<L, TAU, 2, 2, 3, MLO, MHI, MLO>(row, xr, xi);
        frag_ms<L, TAU, 3, 3, 1, MLO, MHI, MLO>(row, xr, xi);
        frag_ms<L, TAU, 4, 3, 2, MLO, MHI, MLO>(row, xr, xi);
        frag_ms<L, TAU, 5, 3, 3, MLO, MHI, MLO>(row, xr, xi);
    }
    store_stage<60, 312>(sm, out, base, tid);

    // ---- l = 4, stage B: m = 1..4, chunk 48 @ off 372 ----
    {
        constexpr int L = 4, TAU = 6, MLO = 1, MHI = 4;
        frag_ms<L, TAU, 0, 1, 3, MLO, MHI, MLO>(row, xr, xi);
        frag_ms<L, TAU, 1, 2, 2, MLO, MHI, MLO>(row, xr, xi);
        frag_ms<L, TAU, 2, 2, 3, MLO, MHI, MLO>(row, xr, xi);
        frag_ms<L, TAU, 3, 3, 1, MLO, MHI, MLO>(row, xr, xi);
        frag_ms<L, TAU, 4, 3, 2, MLO, MHI, MLO>(row, xr, xi);
        frag_ms<L, TAU, 5, 3, 3, MLO, MHI, MLO>(row, xr, xi);
    }
    store_stage<48, 372>(sm, out, base, tid);

    // ---- l = 5 (tau=3), m = -5..5, chunk 66 @ off 420 ----
    {
        constexpr int L = 5, TAU = 3, MLO = -5, MHI = 5;
        frag_ms<L, TAU, 0, 2, 3, MLO, MHI, MLO>(row, xr, xi);
        frag_ms<L, TAU, 1, 3, 2, MLO, MHI, MLO>(row, xr, xi);
        frag_ms<L, TAU, 2, 3, 3, MLO, MHI, MLO>(row, xr, xi);
    }
    store_stage<66, 420>(sm, out, base, tid);

    // ---- l = 6 (tau=1), m = -6..6, chunk 26 @ off 486 ----
    {
        constexpr int L = 6, TAU = 1, MLO = -6, MHI = 6;
        frag_ms<L, TAU, 0, 3, 3, MLO, MHI, MLO>(row, xr, xi);
    }
    store_stage<26, 486>(sm, out, base, tid);
}

extern "C" void kernel_launch(void* const* d_in, const int* in_sizes, int n_in,
                              void* d_out, int out_size) {
    // Defensive: map inputs by element count (all four are distinct).
    const float* xp[4] = {nullptr, nullptr, nullptr, nullptr};
    for (int i = 0; i < n_in && i < 8; ++i) {
        const int s = in_sizes[i];
        if      (s == NB * 2)  xp[0] = (const float*)d_in[i];
        else if (s == NB * 6)  xp[1] = (const float*)d_in[i];
        else if (s == NB * 10) xp[2] = (const float*)d_in[i];
        else if (s == NB * 14) xp[3] = (const float*)d_in[i];
    }
    cgprod_kernel<<<NB / TPB, TPB>>>(xp[0], xp[1], xp[2], xp[3], (float*)d_out);
}

// round 6
// speedup vs baseline: 1.2517x; 1.0046x over previous
#include <cuda_runtime.h>
#include <cstddef>

#define TPB 128
#define SMSTRIDE 82           // >= max stage chunk (80), keeps 2-way-max bank conflicts

static constexpr int NB = 131072;

// ---------------------------------------------------------------------------
// Compile-time Clebsch-Gordan coefficients (Racah formula), double precision,
// evaluated entirely by the compiler. Includes a constexpr Newton sqrt since
// std::sqrt is not constexpr in C++17.
// ---------------------------------------------------------------------------
__host__ __device__ constexpr double factd(int n) {
    double r = 1.0;
    for (int i = 2; i <= n; ++i) r *= (double)i;
    return r;
}
__host__ __device__ constexpr double csqrt(double x) {
    if (x <= 0.0) return 0.0;
    double g = x > 1.0 ? x : 1.0;
    for (int i = 0; i < 100; ++i) g = 0.5 * (g + x / g);
    return g;
}
__host__ __device__ constexpr int iabs_c(int x) { return x < 0 ? -x : x; }
__host__ __device__ constexpr int imin6(int a, int b, int c, int d, int e, int f) {
    int m = a;
    if (b < m) m = b; if (c < m) m = c; if (d < m) m = d;
    if (e < m) m = e; if (f < m) m = f;
    return m;
}

__host__ __device__ constexpr double cgco(int j1, int m1, int j2, int m2, int j, int m) {
    if (m1 + m2 != m) return 0.0;
    if (j < iabs_c(j1 - j2) || j > j1 + j2) return 0.0;
    if (iabs_c(m) > j || iabs_c(m1) > j1 || iabs_c(m2) > j2) return 0.0;
    double pre = csqrt((2.0 * j + 1.0) * factd(j1 + j2 - j) * factd(j + j1 - j2) *
                       factd(j + j2 - j1) / factd(j1 + j2 + j + 1));
    pre *= csqrt(factd(j + m) * factd(j - m) * factd(j1 + m1) * factd(j1 - m1) *
                 factd(j2 + m2) * factd(j2 - m2));
    double s = 0.0;
    for (int k = 0; k <= j1 + j2 - j; ++k) {
        const int d1 = k;
        const int d2 = j1 + j2 - j - k;
        const int d3 = j1 - m1 - k;
        const int d4 = j2 + m2 - k;
        const int d5 = j - j2 + m1 + k;
        const int d6 = j - j1 - m2 + k;
        if (imin6(d1, d2, d3, d4, d5, d6) < 0) continue;
        const double denom = factd(d1) * factd(d2) * factd(d3) * factd(d4) * factd(d5) * factd(d6);
        s += ((k & 1) ? -1.0 : 1.0) / denom;
    }
    return pre * s;
}

// Register-array offset for input part l (sizes 1,3,5,7 -> offsets 0,1,4,9)
template <int L>
__host__ __device__ constexpr int xoff() { return L == 0 ? 0 : (L == 1 ? 1 : (L == 2 ? 4 : 9)); }

// ---------------------------------------------------------------------------
// Template-unrolled accumulation: sum over m1 for one (l1,l2,l,m) entry set.
// All CG coefficients become FFMA immediates; zero coefficients are pruned.
// ---------------------------------------------------------------------------
template <int L1, int L2, int L, int M, int M1>
__device__ __forceinline__ void acc_m1(float& fr, float& fi, const float* xr, const float* xi) {
    constexpr int M2 = M - M1;
    if constexpr (M2 >= -L2 && M2 <= L2) {
        constexpr double Cd = cgco(L1, M1, L2, M2, L, M);
        if constexpr (Cd != 0.0) {
            constexpr float C = (float)Cd;
            const float a = xr[xoff<L1>() + M1 + L1];
            const float b = xi[xoff<L1>() + M1 + L1];
            const float c = xr[xoff<L2>() + M2 + L2];
            const float d = xi[xoff<L2>() + M2 + L2];
            const float pr = fmaf(-b, d, a * c);   // Re(x*y)
            const float pi = fmaf( b, c, a * d);   // Im(x*y)
            fr = fmaf(C, pr, fr);
            fi = fmaf(C, pi, fi);
        }
    }
    if constexpr (M1 < L1) acc_m1<L1, L2, L, M, M1 + 1>(fr, fi, xr, xi);
}

// One fragment (l1,l2) contributing to output l, for m in [MLO, MHI].
// Writes (fr,fi) into the thread's smem row at chunk position ((m-MLO)*TAU+FI)*2.
template <int L, int TAU, int FI, int L1, int L2, int MLO, int MHI, int M>
__device__ __forceinline__ void frag_ms(float* row, const float* xr, const float* xi) {
    float fr = 0.0f, fi2 = 0.0f;
    acc_m1<L1, L2, L, M, (-L1)>(fr, fi2, xr, xi);
    row[((M - MLO) * TAU + FI) * 2 + 0] = fr;
    row[((M - MLO) * TAU + FI) * 2 + 1] = fi2;
    if constexpr (M < MHI) frag_ms<L, TAU, FI, L1, L2, MLO, MHI, M + 1>(row, xr, xi);
}

// Cooperative coalesced store of one staged chunk: smem tile -> out rows.
// CHUNK floats per element (even), OFF = float offset inside the 512-float row.
template <int CHUNK, int OFF>
__device__ __forceinline__ void store_stage(const float* sm, float* __restrict__ out,
                                            int base, int tid) {
    __syncthreads();
    constexpr int C2 = CHUNK / 2;
    #pragma unroll 4
    for (int u = tid; u < TPB * C2; u += TPB) {
        const int e = u / C2;
        const int j = u - e * C2;
        const float2 v = *reinterpret_cast<const float2*>(sm + e * SMSTRIDE + 2 * j);
        *reinterpret_cast<float2*>(out + (size_t)(base + e) * 512 + OFF + 2 * j) = v;
    }
    __syncthreads();
}

// ---------------------------------------------------------------------------
// Main kernel: one thread per batch element.
// Output layout per element (512 floats):
//   l=0: off   0, tau 4   | l=1: off   8, tau 9 | l=2: off  62, tau 11
//   l=3: off 172, tau 10  | l=4: off 312, tau 6 | l=5: off 420, tau 3
//   l=6: off 486, tau 1
// Large chunks are split by m so the smem stage stays <= 80 floats/element.
// ---------------------------------------------------------------------------
__global__ void __launch_bounds__(TPB, 4)
cgprod_kernel(const float* __restrict__ x0, const float* __restrict__ x1,
              const float* __restrict__ x2, const float* __restrict__ x3,
              float* __restrict__ out) {
    __shared__ float sm[TPB * SMSTRIDE];
    const int tid  = threadIdx.x;
    const int base = blockIdx.x * TPB;
    const int b    = base + tid;

    float xr[16], xi[16];
    {
        const float2 v = reinterpret_cast<const float2*>(x0)[b];
        xr[0] = v.x; xi[0] = v.y;
    }
    {
        const float2* p = reinterpret_cast<const float2*>(x1) + (size_t)b * 3;
        #pragma unroll
        for (int k = 0; k < 3; ++k) { const float2 v = p[k]; xr[1 + k] = v.x; xi[1 + k] = v.y; }
    }
    {
        const float2* p = reinterpret_cast<const float2*>(x2) + (size_t)b * 5;
        #pragma unroll
        for (int k = 0; k < 5; ++k) { const float2 v = p[k]; xr[4 + k] = v.x; xi[4 + k] = v.y; }
    }
    {
        const float2* p = reinterpret_cast<const float2*>(x3) + (size_t)b * 7;
        #pragma unroll
        for (int k = 0; k < 7; ++k) { const float2 v = p[k]; xr[9 + k] = v.x; xi[9 + k] = v.y; }
    }

    float* row = sm + tid * SMSTRIDE;

    // ---- l = 0 (tau=4), m = 0, chunk 8 @ off 0 ----
    {
        constexpr int L = 0, TAU = 4, MLO = 0, MHI = 0;
        frag_ms<L, TAU, 0, 0, 0, MLO, MHI, MLO>(row, xr, xi);
        frag_ms<L, TAU, 1, 1, 1, MLO, MHI, MLO>(row, xr, xi);
        frag_ms<L, TAU, 2, 2, 2, MLO, MHI, MLO>(row, xr, xi);
        frag_ms<L, TAU, 3, 3, 3, MLO, MHI, MLO>(row, xr, xi);
    }
    store_stage<8, 0>(sm, out, base, tid);

    // ---- l = 1 (tau=9), m = -1..1, chunk 54 @ off 8 ----
    {
        constexpr int L = 1, TAU = 9, MLO = -1, MHI = 1;
        frag_ms<L, TAU, 0, 0, 1, MLO, MHI, MLO>(row, xr, xi);
        frag_ms<L, TAU, 1, 1, 0, MLO, MHI, MLO>(row, xr, xi);
        frag_ms<L, TAU, 2, 1, 1, MLO, MHI, MLO>(row, xr, xi);
        frag_ms<L, TAU, 3, 1, 2, MLO, MHI, MLO>(row, xr, xi);
        frag_ms<L, TAU, 4, 2, 1, MLO, MHI, MLO>(row, xr, xi);
        frag_ms<L, TAU, 5, 2, 2, MLO, MHI, MLO>(row, xr, xi);
        frag_ms<L, TAU, 6, 2, 3, MLO, MHI, MLO>(row, xr, xi);
        frag_ms<L, TAU, 7, 3, 2, MLO, MHI, MLO>(row, xr, xi);
        frag_ms<L, TAU, 8, 3, 3, MLO, MHI, MLO>(row, xr, xi);
    }
    store_stage<54, 8>(sm, out, base, tid);

    // ---- l = 2 (tau=11), stage A: m = -2..0, chunk 66 @ off 62 ----
    {
        constexpr int L = 2, TAU = 11, MLO = -2, MHI = 0;
        frag_ms<L, TAU,  0, 0, 2, MLO, MHI, MLO>(row, xr, xi);
        frag_ms<L, TAU,  1, 1, 1, MLO, MHI, MLO>(row, xr, xi);
        frag_ms<L, TAU,  2, 1, 2, MLO, MHI, MLO>(row, xr, xi);
        frag_ms<L, TAU,  3, 1, 3, MLO, MHI, MLO>(row, xr, xi);
        frag_ms<L, TAU,  4, 2, 0, MLO, MHI, MLO>(row, xr, xi);
        frag_ms<L, TAU,  5, 2, 1, MLO, MHI, MLO>(row, xr, xi);
        frag_ms<L, TAU,  6, 2, 2, MLO, MHI, MLO>(row, xr, xi);
        frag_ms<L, TAU,  7, 2, 3, MLO, MHI, MLO>(row, xr, xi);
        frag_ms<L, TAU,  8, 3, 1, MLO, MHI, MLO>(row, xr, xi);
        frag_ms<L, TAU,  9, 3, 2, MLO, MHI, MLO>(row, xr, xi);
        frag_ms<L, TAU, 10, 3, 3, MLO, MHI, MLO>(row, xr, xi);
    }
    store_stage<66, 62>(sm, out, base, tid);

    // ---- l = 2, stage B: m = 1..2, chunk 44 @ off 128 ----
    {
        constexpr int L = 2, TAU = 11, MLO = 1, MHI = 2;
        frag_ms<L, TAU,  0, 0, 2, MLO, MHI, MLO>(row, xr, xi);
        frag_ms<L, TAU,  1, 1, 1, MLO, MHI, MLO>(row, xr, xi);
        frag_ms<L, TAU,  2, 1, 2, MLO, MHI, MLO>(row, xr, xi);
        frag_ms<L, TAU,  3, 1, 3, MLO, MHI, MLO>(row, xr, xi);
        frag_ms<L, TAU,  4, 2, 0, MLO, MHI, MLO>(row, xr, xi);
        frag_ms<L, TAU,  5, 2, 1, MLO, MHI, MLO>(row, xr, xi);
        frag_ms<L, TAU,  6, 2, 2, MLO, MHI, MLO>(row, xr, xi);
        frag_ms<L, TAU,  7, 2, 3, MLO, MHI, MLO>(row, xr, xi);
        frag_ms<L, TAU,  8, 3, 1, MLO, MHI, MLO>(row, xr, xi);
        frag_ms<L, TAU,  9, 3, 2, MLO, MHI, MLO>(row, xr, xi);
        frag_ms<L, TAU, 10, 3, 3, MLO, MHI, MLO>(row, xr, xi);
    }
    store_stage<44, 128>(sm, out, base, tid);

    // ---- l = 3 (tau=10), stage A: m = -3..0, chunk 80 @ off 172 ----
    {
        constexpr int L = 3, TAU = 10, MLO = -3, MHI = 0;
        frag_ms<L, TAU, 0, 0, 3, MLO, MHI, MLO>(row, xr, xi);
        frag_ms<L, TAU, 1, 1, 2, MLO, MHI, MLO>(row, xr, xi);
        frag_ms<L, TAU, 2, 1, 3, MLO, MHI, MLO>(row, xr, xi);
        frag_ms<L, TAU, 3, 2, 1, MLO, MHI, MLO>(row, xr, xi);
        frag_ms<L, TAU, 4, 2, 2, MLO, MHI, MLO>(row, xr, xi);
        frag_ms<L, TAU, 5, 2, 3, MLO, MHI, MLO>(row, xr, xi);
        frag_ms<L, TAU, 6, 3, 0, MLO, MHI, MLO>(row, xr, xi);
        frag_ms<L, TAU, 7, 3, 1, MLO, MHI, MLO>(row, xr, xi);
        frag_ms<L, TAU, 8, 3, 2, MLO, MHI, MLO>(row, xr, xi);
        frag_ms<L, TAU, 9, 3, 3, MLO, MHI, MLO>(row, xr, xi);
    }
    store_stage<80, 172>(sm, out, base, tid);

    // ---- l = 3, stage B: m = 1..3, chunk 60 @ off 252 ----
    {
        constexpr int L = 3, TAU = 10, MLO = 1, MHI = 3;
        frag_ms<L, TAU, 0, 0, 3, MLO, MHI, MLO>(row, xr, xi);
        frag_ms<L, TAU, 1, 1, 2, MLO, MHI, MLO>(row, xr, xi);
        frag_ms<L, TAU, 2, 1, 3, MLO, MHI, MLO>(row, xr, xi);
        frag_ms<L, TAU, 3, 2, 1, MLO, MHI, MLO>(row, xr, xi);
        frag_ms<L, TAU, 4, 2, 2, MLO, MHI, MLO>(row, xr, xi);
        frag_ms<L, TAU, 5, 2, 3, MLO, MHI, MLO>(row, xr, xi);
        frag_ms<L, TAU, 6, 3, 0, MLO, MHI, MLO>(row, xr, xi);
        frag_ms<L, TAU, 7, 3, 1, MLO, MHI, MLO>(row, xr, xi);
        frag_ms<L, TAU, 8, 3, 2, MLO, MHI, MLO>(row, xr, xi);
        frag_ms<L, TAU, 9, 3, 3, MLO, MHI, MLO>(row, xr, xi);
    }
    store_stage<60, 252>(sm, out, base, tid);

    // ---- l = 4 (tau=6), stage A: m = -4..0, chunk 60 @ off 312 ----
    {
        constexpr int L = 4, TAU = 6, MLO = -4, MHI = 0;
        frag_ms<L, TAU, 0, 1, 3, MLO, MHI, MLO>(row, xr, xi);
        frag_ms<L, TAU, 1, 2, 2, MLO, MHI, MLO>(row, xr, xi);
        frag_ms<L, TAU, 2, 2, 3, MLO, MHI, MLO>(row, xr, xi);
        frag_ms<L, TAU, 3, 3, 1, MLO, MHI, MLO>(row, xr, xi);
        frag_ms<L, TAU, 4, 3, 2, MLO, MHI, MLO>(row, xr, xi);
        frag_ms<L, TAU, 5, 3, 3, MLO, MHI, MLO>(row, xr, xi);
    }
    store_stage<60, 312>(sm, out, base, tid);

    // ---- l = 4, stage B: m = 1..4, chunk 48 @ off 372 ----
    {
        constexpr int L = 4, TAU = 6, MLO = 1, MHI = 4;
        frag_ms<L, TAU, 0, 1, 3, MLO, MHI, MLO>(row, xr, xi);
        frag_ms<L, TAU, 1, 2, 2, MLO, MHI, MLO>(row, xr, xi);
        frag_ms<L, TAU, 2, 2, 3, MLO, MHI, MLO>(row, xr, xi);
        frag_ms<L, TAU, 3, 3, 1, MLO, MHI, MLO>(row, xr, xi);
        frag_ms<L, TAU, 4, 3, 2, MLO, MHI, MLO>(row, xr, xi);
        frag_ms<L, TAU, 5, 3, 3, MLO, MHI, MLO>(row, xr, xi);
    }
    store_stage<48, 372>(sm, out, base, tid);

    // ---- l = 5 (tau=3), m = -5..5, chunk 66 @ off 420 ----
    {
        constexpr int L = 5, TAU = 3, MLO = -5, MHI = 5;
        frag_ms<L, TAU, 0, 2, 3, MLO, MHI, MLO>(row, xr, xi);
        frag_ms<L, TAU, 1, 3, 2, MLO, MHI, MLO>(row, xr, xi);
        frag_ms<L, TAU, 2, 3, 3, MLO, MHI, MLO>(row, xr, xi);
    }
    store_stage<66, 420>(sm, out, base, tid);

    // ---- l = 6 (tau=1), m = -6..6, chunk 26 @ off 486 ----
    {
        constexpr int L = 6, TAU = 1, MLO = -6, MHI = 6;
        frag_ms<L, TAU, 0, 3, 3, MLO, MHI, MLO>(row, xr, xi);
    }
    store_stage<26, 486>(sm, out, base, tid);
}

extern "C" void kernel_launch(void* const* d_in, const int* in_sizes, int n_in,
                              void* d_out, int out_size) {
    // Defensive: map inputs by element count (all four are distinct).
    const float* xp[4] = {nullptr, nullptr, nullptr, nullptr};
    for (int i = 0; i < n_in && i < 8; ++i) {
        const int s = in_sizes[i];
        if      (s == NB * 2)  xp[0] = (const float*)d_in[i];
        else if (s == NB * 6)  xp[1] = (const float*)d_in[i];
        else if (s == NB * 10) xp[2] = (const float*)d_in[i];
        else if (s == NB * 14) xp[3] = (const float*)d_in[i];
    }
    cgprod_kernel<<<NB / TPB, TPB>>>(xp[0], xp[1], xp[2], xp[3], (float*)d_out);
}